// round 15
// baseline (speedup 1.0000x reference)
#include <cuda_runtime.h>
#include <cstdint>

#define BNS 0.9999950000375f  // 1/sqrt(1+1e-5)
constexpr int B = 16;
constexpr int N = 2048;

// ----------------- device scratch (no allocations) -----------------
__device__ float  g_xx[B * N];
__device__ int    g_idx[B * N * 20];
__device__ float  g_xc[(size_t)B * 512 * N];        // channel-major concat feats
__device__ float  g_pq[(size_t)B * N * 512];        // point-major P|Q per stage
__device__ float2 g_part[(size_t)B * 1024 * 16];    // conv5 partial (max,sum) per col-tile
__device__ float  g_wcat[128 * 512];                // Wt_cat: C x 2O
__device__ float  g_w5t[512 * 1024];
__device__ float  g_pool[B * 2048];
__device__ float  g_h1[B * 512];
__device__ float  g_h2[B * 256];

// ----------------- helpers -----------------
// build Wt_cat (C x 2O): cols [0,O) = Wd = W[:,0:C]; cols [O,2O) = Wc - Wd
__global__ void k_wprep(const float* __restrict__ W, int O, int C, float* __restrict__ Wt) {
    int t = blockIdx.x * 256 + threadIdx.x;
    if (t >= O * C) return;
    int o = t / C, c = t - o * C;
    float wd = W[(size_t)o * 2 * C + c];
    float wc = W[(size_t)o * 2 * C + C + c];
    Wt[(size_t)c * 2 * O + o] = wd;
    Wt[(size_t)c * 2 * O + O + o] = wc - wd;
}

// W (O x rstride) cols [0,C) -> Wt (C x O)
__global__ void k_trs(const float* __restrict__ W, int rstride, int O, int C,
                      float* __restrict__ Wt) {
    int t = blockIdx.x * 256 + threadIdx.x;
    if (t >= O * C) return;
    int o = t / C, c = t - o * C;
    Wt[(size_t)c * O + o] = W[(size_t)o * rstride + c];
}

__global__ void k_xx(const float* __restrict__ F, size_t bstride, int C,
                     float* __restrict__ xx) {
    int b = blockIdx.y, i = blockIdx.x * 256 + threadIdx.x;
    const float* Fb = F + (size_t)b * bstride;
    float s = 0.f;
    for (int c = 0; c < C; c++) { float v = Fb[(size_t)c * N + i]; s = fmaf(v, v, s); }
    xx[b * N + i] = s;
}

// ----------------- fused kNN: 64x64 dist tile GEMM (4x4/thread) + warp top-20 -----------------
// Selection key: 2*inner(i,j) - xx[j]   (dropping row-constant -xx[i] preserves order)
template <int C>
__global__ __launch_bounds__(256, 2) void k_knn(const float* __restrict__ F, size_t bstride,
                                                const float* __restrict__ xx,
                                                int* __restrict__ idxo) {
    extern __shared__ float sm[];
    float* As  = sm;                 // [C][64]
    float* Bs  = As + C * 64;        // [C][64]
    float* sD  = Bs + C * 64;        // [64][68]
    float* sXj = sD + 64 * 68;       // [64]
    int b = blockIdx.y, i0 = blockIdx.x * 64;
    const float* Fb = F + (size_t)b * bstride;
    int tid = threadIdx.x, lane = tid & 31, w = tid >> 5;
    int tx = tid & 15, ty = tid >> 4;

    for (int t = tid; t < C * 64; t += 256)
        As[t] = Fb[(size_t)(t >> 6) * N + i0 + (t & 63)];

    float val[8]; int idx[8]; float th[8];
#pragma unroll
    for (int r = 0; r < 8; r++) { val[r] = -3e38f; idx[r] = 0; th[r] = -3e38f; }
    __syncthreads();

    for (int j0 = 0; j0 < N; j0 += 64) {
        for (int t = tid; t < C * 64; t += 256)
            Bs[t] = Fb[(size_t)(t >> 6) * N + j0 + (t & 63)];
        if (tid < 64) sXj[tid] = xx[b * N + j0 + tid];
        __syncthreads();

        float acc[4][4] = {};
#pragma unroll 4
        for (int k = 0; k < C; k++) {
            float4 a4 = *(const float4*)&As[k * 64 + ty * 4];
            float4 b4 = *(const float4*)&Bs[k * 64 + tx * 4];
            float a[4] = {a4.x, a4.y, a4.z, a4.w};
            float bv[4] = {b4.x, b4.y, b4.z, b4.w};
#pragma unroll
            for (int i = 0; i < 4; i++)
#pragma unroll
                for (int j = 0; j < 4; j++) acc[i][j] = fmaf(a[i], bv[j], acc[i][j]);
        }
#pragma unroll
        for (int ii = 0; ii < 4; ii++)
#pragma unroll
            for (int jj = 0; jj < 4; jj++)
                sD[(ty * 4 + ii) * 68 + tx * 4 + jj] =
                    2.f * acc[ii][jj] - sXj[tx * 4 + jj];
        __syncthreads();

        // warp w owns rows 8w..8w+7; sorted top-20 in lanes 0..19
#pragma unroll
        for (int r = 0; r < 8; r++) {
            int row = (w << 3) + r;
#pragma unroll
            for (int h = 0; h < 2; h++) {
                float d = sD[row * 68 + h * 32 + lane];
                unsigned ball = __ballot_sync(0xffffffffu, d > th[r]);
                while (ball) {
                    int src = __ffs(ball) - 1;
                    ball &= ball - 1;
                    float xv = __shfl_sync(0xffffffffu, d, src);
                    if (xv <= th[r]) continue;
                    int xj = j0 + h * 32 + src;
                    unsigned bigger = __ballot_sync(0xffffffffu, val[r] > xv);
                    int pos = __popc(bigger & 0xFFFFFu);
                    float upv = __shfl_up_sync(0xffffffffu, val[r], 1);
                    int   upi = __shfl_up_sync(0xffffffffu, idx[r], 1);
                    if (lane == pos)     { val[r] = xv;  idx[r] = xj; }
                    else if (lane > pos) { val[r] = upv; idx[r] = upi; }
                    th[r] = __shfl_sync(0xffffffffu, val[r], 19);
                }
            }
        }
        __syncthreads();
    }
    if (lane < 20) {
#pragma unroll
        for (int r = 0; r < 8; r++)
            idxo[((size_t)b * N + i0 + (w << 3) + r) * 20 + lane] = idx[r];
    }
}

// ----------------- 128x128 tiled GEMM, 8x8/thread, double-buffered smem -----------------
// EPI 1: PM  out[(b*N+col)*M+row] = acc                        (point-major)
// EPI 2: BN+lrelu + partial pool: part[(b*M+row)*16 + bx] = (max_col, sum_col)
template <int EPI>
__global__ __launch_bounds__(256, 2) void k_g128(
    const float* __restrict__ A, size_t a_bs, int lda,
    const float* __restrict__ Bm, size_t b_bs,
    int C, int M, float* __restrict__ out,
    const float* __restrict__ e1, const float* __restrict__ e2,
    float2* __restrict__ part) {
    __shared__ float sA[2][8][128];
    __shared__ float sB[2][8][128];
    __shared__ float redm[128 * 16];
    __shared__ float reds[128 * 16];
    int b = blockIdx.z, o0 = blockIdx.y * 128, n0 = blockIdx.x * 128;
    const float* Ab = A + (size_t)b * a_bs;
    const float* Bb = Bm + (size_t)b * b_bs;
    int tid = threadIdx.x, tx = tid & 15, ty = tid >> 4;
    int lr = tid >> 5, lc = (tid & 31) * 4;
    float acc[8][8] = {};
    int T = (C + 7) / 8;
    float4 ra = make_float4(0.f, 0.f, 0.f, 0.f), rb = ra;
    if (lr < C) {
        ra = *(const float4*)&Ab[(size_t)lr * lda + o0 + lc];
        rb = *(const float4*)&Bb[(size_t)lr * N + n0 + lc];
    }
    int p = 0;
    for (int t = 0; t < T; t++) {
        *(float4*)&sA[p][lr][lc] = ra;
        *(float4*)&sB[p][lr][lc] = rb;
        __syncthreads();
        if (t + 1 < T) {
            int c = (t + 1) * 8 + lr;
            ra = make_float4(0.f, 0.f, 0.f, 0.f); rb = ra;
            if (c < C) {
                ra = *(const float4*)&Ab[(size_t)c * lda + o0 + lc];
                rb = *(const float4*)&Bb[(size_t)c * N + n0 + lc];
            }
        }
#pragma unroll
        for (int kk = 0; kk < 8; kk++) {
            float a[8], bv[8];
            *(float4*)&a[0]  = *(const float4*)&sA[p][kk][ty * 8];
            *(float4*)&a[4]  = *(const float4*)&sA[p][kk][ty * 8 + 4];
            *(float4*)&bv[0] = *(const float4*)&sB[p][kk][tx * 8];
            *(float4*)&bv[4] = *(const float4*)&sB[p][kk][tx * 8 + 4];
#pragma unroll
            for (int i = 0; i < 8; i++)
#pragma unroll
                for (int j = 0; j < 8; j++) acc[i][j] = fmaf(a[i], bv[j], acc[i][j]);
        }
        p ^= 1;
    }
    if (EPI == 1) {
#pragma unroll
        for (int j = 0; j < 8; j++) {
            int col = n0 + tx * 8 + j;
            float* oc = out + ((size_t)b * N + col) * M + o0 + ty * 8;
            float4 v0 = make_float4(acc[0][j], acc[1][j], acc[2][j], acc[3][j]);
            float4 v1 = make_float4(acc[4][j], acc[5][j], acc[6][j], acc[7][j]);
            *(float4*)&oc[0] = v0;
            *(float4*)&oc[4] = v1;
        }
    } else {
#pragma unroll
        for (int i = 0; i < 8; i++) {
            int row = o0 + ty * 8 + i;
            float s = e1[row] * BNS, bi = e2[row];
            float mx = -3e38f, sm = 0.f;
#pragma unroll
            for (int j = 0; j < 8; j++) {
                float v = acc[i][j] * s + bi;
                v = v < 0.f ? 0.2f * v : v;
                mx = fmaxf(mx, v); sm += v;
            }
            redm[(ty * 8 + i) * 16 + tx] = mx;
            reds[(ty * 8 + i) * 16 + tx] = sm;
        }
        __syncthreads();
        if (tid < 128) {
            float mx = -3e38f, sm = 0.f;
#pragma unroll
            for (int t = 0; t < 16; t++) {
                mx = fmaxf(mx, redm[tid * 16 + t]);
                sm += reds[tid * 16 + t];
            }
            part[((size_t)b * M + o0 + tid) * 16 + blockIdx.x] = make_float2(mx, sm);
        }
    }
}

// ----------------- gather-max + BN + lrelu -----------------
template <int O>
__global__ void k_gmax(const float* __restrict__ PQ, const int* __restrict__ idx,
                       const float* __restrict__ g, const float* __restrict__ bb,
                       float* __restrict__ xc, int choff) {
    constexpr int PTS = 256 / O;
    int b = blockIdx.y;
    int n = blockIdx.x * PTS + (threadIdx.x >> (O == 64 ? 6 : (O == 128 ? 7 : 8)));
    int o = threadIdx.x & (O - 1);
    const float* Pb = PQ + (size_t)b * N * (2 * O);
    const int* ir = idx + ((size_t)b * N + n) * 20;
    float m = -3e38f;
#pragma unroll
    for (int k = 0; k < 20; k++) {
        int j = __ldg(&ir[k]);
        m = fmaxf(m, __ldg(&Pb[(size_t)j * (2 * O) + o]));
    }
    float v = m + Pb[(size_t)n * (2 * O) + O + o];
    v = v * (g[o] * BNS) + bb[o];
    v = v < 0.f ? 0.2f * v : v;
    xc[((size_t)b * 512 + choff + o) * N + n] = v;
}

// ----------------- final pooling reduce + FC head -----------------
__global__ void k_pool2(const float2* __restrict__ part, float* __restrict__ p) {
    int t = blockIdx.x * 256 + threadIdx.x;       // 0 .. B*1024-1
    int b = t >> 10, o = t & 1023;
    const float2* pr = part + (size_t)t * 16;
    float mx = -3e38f, s = 0.f;
#pragma unroll
    for (int i = 0; i < 16; i++) { float2 v = pr[i]; mx = fmaxf(mx, v.x); s += v.y; }
    p[b * 2048 + o] = mx;
    p[b * 2048 + 1024 + o] = s * (1.f / 2048.f);
}

template <int MODE>  // 0: +bias, 1: (+bias)+BN+lrelu
__global__ void k_fc(const float* __restrict__ in, int Cin, const float* __restrict__ W,
                     const float* __restrict__ bias, const float* __restrict__ g,
                     const float* __restrict__ bb, int O, float* __restrict__ outp) {
    int gw = (blockIdx.x * blockDim.x + threadIdx.x) >> 5;
    int lane = threadIdx.x & 31;
    if (gw >= 16 * O) return;
    int b = gw / O, o = gw - b * O;
    const float* ib = in + (size_t)b * Cin;
    const float* wr = W + (size_t)o * Cin;
    float s = 0.f;
    for (int c = lane; c < Cin; c += 32) s = fmaf(ib[c], wr[c], s);
#pragma unroll
    for (int off = 16; off; off >>= 1) s += __shfl_xor_sync(0xffffffffu, s, off);
    if (lane == 0) {
        float v = s + (bias ? bias[o] : 0.f);
        if (MODE == 1) { v = v * (g[o] * BNS) + bb[o]; v = v < 0.f ? 0.2f * v : v; }
        outp[b * O + o] = v;
    }
}

static int knn_smem(int C) { return (C * 64 * 2 + 64 * 68 + 64) * 4; }

extern "C" void kernel_launch(void* const* d_in, const int* in_sizes, int n_in,
                              void* d_out, int out_size) {
    (void)in_sizes; (void)n_in; (void)out_size;
    const float* x  = (const float*)d_in[0];
    const float* W1 = (const float*)d_in[1];
    const float* W2 = (const float*)d_in[2];
    const float* W3 = (const float*)d_in[3];
    const float* W4 = (const float*)d_in[4];
    const float* W5 = (const float*)d_in[5];
    const float *gs[7], *bs[7];
    for (int i = 0; i < 7; i++) { gs[i] = (const float*)d_in[6 + 2 * i]; bs[i] = (const float*)d_in[7 + 2 * i]; }
    const float* L1w = (const float*)d_in[20];
    const float* L2w = (const float*)d_in[21];
    const float* L2b = (const float*)d_in[22];
    const float* L3w = (const float*)d_in[23];
    const float* L3b = (const float*)d_in[24];
    float* out = (float*)d_out;

    float *xxp, *xc, *pq, *wcat, *w5t, *poolp, *h1, *h2;
    float2* partp;
    int* idxp;
    cudaGetSymbolAddress((void**)&xxp, g_xx);
    cudaGetSymbolAddress((void**)&idxp, g_idx);
    cudaGetSymbolAddress((void**)&xc, g_xc);
    cudaGetSymbolAddress((void**)&pq, g_pq);
    cudaGetSymbolAddress((void**)&partp, g_part);
    cudaGetSymbolAddress((void**)&wcat, g_wcat);
    cudaGetSymbolAddress((void**)&w5t, g_w5t);
    cudaGetSymbolAddress((void**)&poolp, g_pool);
    cudaGetSymbolAddress((void**)&h1, g_h1);
    cudaGetSymbolAddress((void**)&h2, g_h2);

    cudaFuncSetAttribute(k_knn<3>,   cudaFuncAttributeMaxDynamicSharedMemorySize, knn_smem(3));
    cudaFuncSetAttribute(k_knn<64>,  cudaFuncAttributeMaxDynamicSharedMemorySize, knn_smem(64));
    cudaFuncSetAttribute(k_knn<128>, cudaFuncAttributeMaxDynamicSharedMemorySize, knn_smem(128));

    dim3 thr(256);
    dim3 knng(N / 64, B);
    size_t bs512 = (size_t)512 * N;

    // ---- stage 1: F=x, C=3, O=64, choff=0 ----
    k_wprep<<<1, thr>>>(W1, 64, 3, wcat);
    k_xx<<<dim3(N / 256, B), thr>>>(x, (size_t)3 * N, 3, xxp);
    k_knn<3><<<knng, thr, knn_smem(3)>>>(x, (size_t)3 * N, xxp, idxp);
    k_g128<1><<<dim3(16, 1, B), thr>>>(wcat, 0, 128, x, (size_t)3 * N, 3, 128, pq, nullptr, nullptr, nullptr);
    k_gmax<64><<<dim3(N / 4, B), thr>>>(pq, idxp, gs[0], bs[0], xc, 0);

    // ---- stage 2: F=xc[0:64], C=64, O=64, choff=64 ----
    const float* F2 = xc;
    k_wprep<<<16, thr>>>(W2, 64, 64, wcat);
    k_xx<<<dim3(N / 256, B), thr>>>(F2, bs512, 64, xxp);
    k_knn<64><<<knng, thr, knn_smem(64)>>>(F2, bs512, xxp, idxp);
    k_g128<1><<<dim3(16, 1, B), thr>>>(wcat, 0, 128, F2, bs512, 64, 128, pq, nullptr, nullptr, nullptr);
    k_gmax<64><<<dim3(N / 4, B), thr>>>(pq, idxp, gs[1], bs[1], xc, 64);

    // ---- stage 3: F=xc[64:128], C=64, O=128, choff=128 ----
    const float* F3 = xc + (size_t)64 * N;
    k_wprep<<<32, thr>>>(W3, 128, 64, wcat);
    k_xx<<<dim3(N / 256, B), thr>>>(F3, bs512, 64, xxp);
    k_knn<64><<<knng, thr, knn_smem(64)>>>(F3, bs512, xxp, idxp);
    k_g128<1><<<dim3(16, 2, B), thr>>>(wcat, 0, 256, F3, bs512, 64, 256, pq, nullptr, nullptr, nullptr);
    k_gmax<128><<<dim3(N / 2, B), thr>>>(pq, idxp, gs[2], bs[2], xc, 128);

    // ---- stage 4: F=xc[128:256], C=128, O=256, choff=256 ----
    const float* F4 = xc + (size_t)128 * N;
    k_wprep<<<128, thr>>>(W4, 256, 128, wcat);
    k_xx<<<dim3(N / 256, B), thr>>>(F4, bs512, 128, xxp);
    k_knn<128><<<knng, thr, knn_smem(128)>>>(F4, bs512, xxp, idxp);
    k_g128<1><<<dim3(16, 4, B), thr>>>(wcat, 0, 512, F4, bs512, 128, 512, pq, nullptr, nullptr, nullptr);
    k_gmax<256><<<dim3(N, B), thr>>>(pq, idxp, gs[3], bs[3], xc, 256);

    // ---- conv5 (+fused partial pooling) + head ----
    k_trs<<<2048, thr>>>(W5, 512, 1024, 512, w5t);
    k_g128<2><<<dim3(16, 8, B), thr>>>(w5t, 0, 1024, xc, bs512, 512, 1024, nullptr, gs[4], bs[4], partp);
    k_pool2<<<(B * 1024) / 256, thr>>>(partp, poolp);
    k_fc<1><<<(16 * 512 * 32) / 256, thr>>>(poolp, 2048, L1w, nullptr, gs[5], bs[5], 512, h1);
    k_fc<1><<<(16 * 256 * 32) / 256, thr>>>(h1, 512, L2w, L2b, gs[6], bs[6], 256, h2);
    k_fc<0><<<(16 * 40 * 32 + 255) / 256, thr>>>(h2, 256, L3w, L3b, nullptr, nullptr, 40, out);
}

// round 16
// speedup vs baseline: 1.0788x; 1.0788x over previous
#include <cuda_runtime.h>
#include <cstdint>

#define BNS 0.9999950000375f  // 1/sqrt(1+1e-5)
constexpr int B = 16;
constexpr int N = 2048;

// ----------------- device scratch (no allocations) -----------------
__device__ float  g_xx[B * N];
__device__ int    g_idx[B * N * 20];
__device__ float  g_xc[(size_t)B * 512 * N];        // channel-major concat feats
__device__ float  g_pq[(size_t)B * N * 512];        // point-major P|Q per stage
__device__ float2 g_part[(size_t)B * 1024 * 16];    // conv5 partial (max,sum) per col-tile
__device__ float  g_wcat[128 * 512];                // Wt_cat: C x 2O
__device__ float  g_w5t[512 * 1024];
__device__ float  g_pool[B * 2048];
__device__ float  g_h1[B * 512];
__device__ float  g_h2[B * 256];

// ----------------- helpers -----------------
__global__ void k_wprep(const float* __restrict__ W, int O, int C, float* __restrict__ Wt) {
    int t = blockIdx.x * 256 + threadIdx.x;
    if (t >= O * C) return;
    int o = t / C, c = t - o * C;
    float wd = W[(size_t)o * 2 * C + c];
    float wc = W[(size_t)o * 2 * C + C + c];
    Wt[(size_t)c * 2 * O + o] = wd;
    Wt[(size_t)c * 2 * O + O + o] = wc - wd;
}

__global__ void k_trs(const float* __restrict__ W, int rstride, int O, int C,
                      float* __restrict__ Wt) {
    int t = blockIdx.x * 256 + threadIdx.x;
    if (t >= O * C) return;
    int o = t / C, c = t - o * C;
    Wt[(size_t)c * O + o] = W[(size_t)o * rstride + c];
}

__global__ void k_xx(const float* __restrict__ F, size_t bstride, int C,
                     float* __restrict__ xx) {
    int b = blockIdx.y, i = blockIdx.x * 256 + threadIdx.x;
    const float* Fb = F + (size_t)b * bstride;
    float s = 0.f;
    for (int c = 0; c < C; c++) { float v = Fb[(size_t)c * N + i]; s = fmaf(v, v, s); }
    xx[b * N + i] = s;
}

// ----------------- fused kNN: 64x128 dist tile GEMM (4x8/thread) + warp top-20 -----------------
// Selection key: 2*inner(i,j) - xx[j]   (dropping row-constant -xx[i] preserves order)
template <int C>
__global__ __launch_bounds__(256, 2) void k_knn(const float* __restrict__ F, size_t bstride,
                                                const float* __restrict__ xx,
                                                int* __restrict__ idxo) {
    constexpr int KC = (C < 32) ? C : 32;
    extern __shared__ float sm[];
    float* As  = sm;                 // [C][64]
    float* Bs  = As + C * 64;        // [KC][128]
    float* sD  = Bs + KC * 128;      // [64][132]
    float* sXj = sD + 64 * 132;      // [128]
    int b = blockIdx.y, i0 = blockIdx.x * 64;
    const float* Fb = F + (size_t)b * bstride;
    int tid = threadIdx.x, lane = tid & 31, w = tid >> 5;
    int tx = tid & 15, ty = tid >> 4;

    for (int t = tid; t < C * 64; t += 256)
        As[t] = Fb[(size_t)(t >> 6) * N + i0 + (t & 63)];

    float val[8]; int idx[8]; float th[8];
#pragma unroll
    for (int r = 0; r < 8; r++) { val[r] = -3e38f; idx[r] = 0; th[r] = -3e38f; }

    for (int j0 = 0; j0 < N; j0 += 128) {
        __syncthreads();   // previous tile's selection done (and As ready on first pass)
        if (tid < 128) sXj[tid] = xx[b * N + j0 + tid];
        float acc[4][8] = {};
        for (int c0 = 0; c0 < C; c0 += KC) {
            if (c0) __syncthreads();
            for (int t = tid; t < KC * 128; t += 256)
                Bs[t] = Fb[(size_t)(c0 + (t >> 7)) * N + j0 + (t & 127)];
            __syncthreads();
#pragma unroll 8
            for (int kk = 0; kk < KC; kk++) {
                float4 a4 = *(const float4*)&As[(c0 + kk) * 64 + ty * 4];
                float4 b0 = *(const float4*)&Bs[kk * 128 + tx * 4];
                float4 b1 = *(const float4*)&Bs[kk * 128 + 64 + tx * 4];
                float a[4] = {a4.x, a4.y, a4.z, a4.w};
                float bv[8] = {b0.x, b0.y, b0.z, b0.w, b1.x, b1.y, b1.z, b1.w};
#pragma unroll
                for (int i = 0; i < 4; i++)
#pragma unroll
                    for (int j = 0; j < 8; j++) acc[i][j] = fmaf(a[i], bv[j], acc[i][j]);
            }
        }
        __syncthreads();
#pragma unroll
        for (int ii = 0; ii < 4; ii++)
#pragma unroll
            for (int jj = 0; jj < 8; jj++) {
                int cl = (jj < 4) ? (tx * 4 + jj) : (64 + tx * 4 + jj - 4);
                sD[(ty * 4 + ii) * 132 + cl] = 2.f * acc[ii][jj] - sXj[cl];
            }
        __syncthreads();

        // warp w owns rows 8w..8w+7; sorted top-20 in lanes 0..19
#pragma unroll
        for (int r = 0; r < 8; r++) {
            int row = (w << 3) + r;
#pragma unroll
            for (int h = 0; h < 4; h++) {
                float d = sD[row * 132 + h * 32 + lane];
                unsigned ball = __ballot_sync(0xffffffffu, d > th[r]);
                while (ball) {
                    int src = __ffs(ball) - 1;
                    ball &= ball - 1;
                    float xv = __shfl_sync(0xffffffffu, d, src);
                    if (xv <= th[r]) continue;
                    int xj = j0 + h * 32 + src;
                    unsigned bigger = __ballot_sync(0xffffffffu, val[r] > xv);
                    int pos = __popc(bigger & 0xFFFFFu);
                    float upv = __shfl_up_sync(0xffffffffu, val[r], 1);
                    int   upi = __shfl_up_sync(0xffffffffu, idx[r], 1);
                    if (lane == pos)     { val[r] = xv;  idx[r] = xj; }
                    else if (lane > pos) { val[r] = upv; idx[r] = upi; }
                    th[r] = __shfl_sync(0xffffffffu, val[r], 19);
                }
            }
        }
    }
    if (lane < 20) {
#pragma unroll
        for (int r = 0; r < 8; r++)
            idxo[((size_t)b * N + i0 + (w << 3) + r) * 20 + lane] = idx[r];
    }
}

// ----------------- 128x128 tiled GEMM, 8x8/thread, double-buffered smem -----------------
// EPI 1: PM  out[(b*N+col)*M+row] = acc                        (point-major)
// EPI 2: BN+lrelu + partial pool: part[(b*M+row)*16 + bx] = (max_col, sum_col)
template <int EPI>
__global__ __launch_bounds__(256, 2) void k_g128(
    const float* __restrict__ A, size_t a_bs, int lda,
    const float* __restrict__ Bm, size_t b_bs,
    int C, int M, float* __restrict__ out,
    const float* __restrict__ e1, const float* __restrict__ e2,
    float2* __restrict__ part) {
    __shared__ float sA[2][8][128];
    __shared__ float sB[2][8][128];
    __shared__ float redm[128 * 16];
    __shared__ float reds[128 * 16];
    int b = blockIdx.z, o0 = blockIdx.y * 128, n0 = blockIdx.x * 128;
    const float* Ab = A + (size_t)b * a_bs;
    const float* Bb = Bm + (size_t)b * b_bs;
    int tid = threadIdx.x, tx = tid & 15, ty = tid >> 4;
    int lr = tid >> 5, lc = (tid & 31) * 4;
    float acc[8][8] = {};
    int T = (C + 7) / 8;
    float4 ra = make_float4(0.f, 0.f, 0.f, 0.f), rb = ra;
    if (lr < C) {
        ra = *(const float4*)&Ab[(size_t)lr * lda + o0 + lc];
        rb = *(const float4*)&Bb[(size_t)lr * N + n0 + lc];
    }
    int p = 0;
    for (int t = 0; t < T; t++) {
        *(float4*)&sA[p][lr][lc] = ra;
        *(float4*)&sB[p][lr][lc] = rb;
        __syncthreads();
        if (t + 1 < T) {
            int c = (t + 1) * 8 + lr;
            ra = make_float4(0.f, 0.f, 0.f, 0.f); rb = ra;
            if (c < C) {
                ra = *(const float4*)&Ab[(size_t)c * lda + o0 + lc];
                rb = *(const float4*)&Bb[(size_t)c * N + n0 + lc];
            }
        }
#pragma unroll
        for (int kk = 0; kk < 8; kk++) {
            float a[8], bv[8];
            *(float4*)&a[0]  = *(const float4*)&sA[p][kk][ty * 8];
            *(float4*)&a[4]  = *(const float4*)&sA[p][kk][ty * 8 + 4];
            *(float4*)&bv[0] = *(const float4*)&sB[p][kk][tx * 4];
            *(float4*)&bv[4] = *(const float4*)&sB[p][kk][64 + tx * 4];
#pragma unroll
            for (int i = 0; i < 8; i++)
#pragma unroll
                for (int j = 0; j < 8; j++) acc[i][j] = fmaf(a[i], bv[j], acc[i][j]);
        }
        p ^= 1;
    }
    if (EPI == 1) {
#pragma unroll
        for (int j = 0; j < 8; j++) {
            int col = n0 + ((j < 4) ? (tx * 4 + j) : (64 + tx * 4 + j - 4));
            float* oc = out + ((size_t)b * N + col) * M + o0 + ty * 8;
            float4 v0 = make_float4(acc[0][j], acc[1][j], acc[2][j], acc[3][j]);
            float4 v1 = make_float4(acc[4][j], acc[5][j], acc[6][j], acc[7][j]);
            *(float4*)&oc[0] = v0;
            *(float4*)&oc[4] = v1;
        }
    } else {
#pragma unroll
        for (int i = 0; i < 8; i++) {
            int row = o0 + ty * 8 + i;
            float s = e1[row] * BNS, bi = e2[row];
            float mx = -3e38f, sm = 0.f;
#pragma unroll
            for (int j = 0; j < 8; j++) {
                float v = acc[i][j] * s + bi;
                v = v < 0.f ? 0.2f * v : v;
                mx = fmaxf(mx, v); sm += v;
            }
            redm[(ty * 8 + i) * 16 + tx] = mx;
            reds[(ty * 8 + i) * 16 + tx] = sm;
        }
        __syncthreads();
        if (tid < 128) {
            float mx = -3e38f, sm = 0.f;
#pragma unroll
            for (int t = 0; t < 16; t++) {
                mx = fmaxf(mx, redm[tid * 16 + t]);
                sm += reds[tid * 16 + t];
            }
            part[((size_t)b * M + o0 + tid) * 16 + blockIdx.x] = make_float2(mx, sm);
        }
    }
}

// ----------------- gather-max + BN + lrelu -----------------
template <int O>
__global__ void k_gmax(const float* __restrict__ PQ, const int* __restrict__ idx,
                       const float* __restrict__ g, const float* __restrict__ bb,
                       float* __restrict__ xc, int choff) {
    constexpr int PTS = 256 / O;
    int b = blockIdx.y;
    int n = blockIdx.x * PTS + (threadIdx.x >> (O == 64 ? 6 : (O == 128 ? 7 : 8)));
    int o = threadIdx.x & (O - 1);
    const float* Pb = PQ + (size_t)b * N * (2 * O);
    const int* ir = idx + ((size_t)b * N + n) * 20;
    float m = -3e38f;
#pragma unroll
    for (int k = 0; k < 20; k++) {
        int j = __ldg(&ir[k]);
        m = fmaxf(m, __ldg(&Pb[(size_t)j * (2 * O) + o]));
    }
    float v = m + Pb[(size_t)n * (2 * O) + O + o];
    v = v * (g[o] * BNS) + bb[o];
    v = v < 0.f ? 0.2f * v : v;
    xc[((size_t)b * 512 + choff + o) * N + n] = v;
}

// ----------------- final pooling reduce + FC head -----------------
__global__ void k_pool2(const float2* __restrict__ part, float* __restrict__ p) {
    int t = blockIdx.x * 256 + threadIdx.x;       // 0 .. B*1024-1
    int b = t >> 10, o = t & 1023;
    const float2* pr = part + (size_t)t * 16;
    float mx = -3e38f, s = 0.f;
#pragma unroll
    for (int i = 0; i < 16; i++) { float2 v = pr[i]; mx = fmaxf(mx, v.x); s += v.y; }
    p[b * 2048 + o] = mx;
    p[b * 2048 + 1024 + o] = s * (1.f / 2048.f);
}

template <int MODE>  // 0: +bias, 1: (+bias)+BN+lrelu
__global__ void k_fc(const float* __restrict__ in, int Cin, const float* __restrict__ W,
                     const float* __restrict__ bias, const float* __restrict__ g,
                     const float* __restrict__ bb, int O, float* __restrict__ outp) {
    int gw = (blockIdx.x * blockDim.x + threadIdx.x) >> 5;
    int lane = threadIdx.x & 31;
    if (gw >= 16 * O) return;
    int b = gw / O, o = gw - b * O;
    const float* ib = in + (size_t)b * Cin;
    const float* wr = W + (size_t)o * Cin;
    float s = 0.f;
    for (int c = lane; c < Cin; c += 32) s = fmaf(ib[c], wr[c], s);
#pragma unroll
    for (int off = 16; off; off >>= 1) s += __shfl_xor_sync(0xffffffffu, s, off);
    if (lane == 0) {
        float v = s + (bias ? bias[o] : 0.f);
        if (MODE == 1) { v = v * (g[o] * BNS) + bb[o]; v = v < 0.f ? 0.2f * v : v; }
        outp[b * O + o] = v;
    }
}

static int knn_smem(int C) {
    int kc = (C < 32) ? C : 32;
    return (C * 64 + kc * 128 + 64 * 132 + 128) * 4;
}

extern "C" void kernel_launch(void* const* d_in, const int* in_sizes, int n_in,
                              void* d_out, int out_size) {
    (void)in_sizes; (void)n_in; (void)out_size;
    const float* x  = (const float*)d_in[0];
    const float* W1 = (const float*)d_in[1];
    const float* W2 = (const float*)d_in[2];
    const float* W3 = (const float*)d_in[3];
    const float* W4 = (const float*)d_in[4];
    const float* W5 = (const float*)d_in[5];
    const float *gs[7], *bs[7];
    for (int i = 0; i < 7; i++) { gs[i] = (const float*)d_in[6 + 2 * i]; bs[i] = (const float*)d_in[7 + 2 * i]; }
    const float* L1w = (const float*)d_in[20];
    const float* L2w = (const float*)d_in[21];
    const float* L2b = (const float*)d_in[22];
    const float* L3w = (const float*)d_in[23];
    const float* L3b = (const float*)d_in[24];
    float* out = (float*)d_out;

    float *xxp, *xc, *pq, *wcat, *w5t, *poolp, *h1, *h2;
    float2* partp;
    int* idxp;
    cudaGetSymbolAddress((void**)&xxp, g_xx);
    cudaGetSymbolAddress((void**)&idxp, g_idx);
    cudaGetSymbolAddress((void**)&xc, g_xc);
    cudaGetSymbolAddress((void**)&pq, g_pq);
    cudaGetSymbolAddress((void**)&partp, g_part);
    cudaGetSymbolAddress((void**)&wcat, g_wcat);
    cudaGetSymbolAddress((void**)&w5t, g_w5t);
    cudaGetSymbolAddress((void**)&poolp, g_pool);
    cudaGetSymbolAddress((void**)&h1, g_h1);
    cudaGetSymbolAddress((void**)&h2, g_h2);

    cudaFuncSetAttribute(k_knn<3>,   cudaFuncAttributeMaxDynamicSharedMemorySize, knn_smem(3));
    cudaFuncSetAttribute(k_knn<64>,  cudaFuncAttributeMaxDynamicSharedMemorySize, knn_smem(64));
    cudaFuncSetAttribute(k_knn<128>, cudaFuncAttributeMaxDynamicSharedMemorySize, knn_smem(128));

    dim3 thr(256);
    dim3 knng(N / 64, B);
    size_t bs512 = (size_t)512 * N;

    // ---- stage 1: F=x, C=3, O=64, choff=0 ----
    k_wprep<<<1, thr>>>(W1, 64, 3, wcat);
    k_xx<<<dim3(N / 256, B), thr>>>(x, (size_t)3 * N, 3, xxp);
    k_knn<3><<<knng, thr, knn_smem(3)>>>(x, (size_t)3 * N, xxp, idxp);
    k_g128<1><<<dim3(16, 1, B), thr>>>(wcat, 0, 128, x, (size_t)3 * N, 3, 128, pq, nullptr, nullptr, nullptr);
    k_gmax<64><<<dim3(N / 4, B), thr>>>(pq, idxp, gs[0], bs[0], xc, 0);

    // ---- stage 2: F=xc[0:64], C=64, O=64, choff=64 ----
    const float* F2 = xc;
    k_wprep<<<16, thr>>>(W2, 64, 64, wcat);
    k_xx<<<dim3(N / 256, B), thr>>>(F2, bs512, 64, xxp);
    k_knn<64><<<knng, thr, knn_smem(64)>>>(F2, bs512, xxp, idxp);
    k_g128<1><<<dim3(16, 1, B), thr>>>(wcat, 0, 128, F2, bs512, 64, 128, pq, nullptr, nullptr, nullptr);
    k_gmax<64><<<dim3(N / 4, B), thr>>>(pq, idxp, gs[1], bs[1], xc, 64);

    // ---- stage 3: F=xc[64:128], C=64, O=128, choff=128 ----
    const float* F3 = xc + (size_t)64 * N;
    k_wprep<<<32, thr>>>(W3, 128, 64, wcat);
    k_xx<<<dim3(N / 256, B), thr>>>(F3, bs512, 64, xxp);
    k_knn<64><<<knng, thr, knn_smem(64)>>>(F3, bs512, xxp, idxp);
    k_g128<1><<<dim3(16, 2, B), thr>>>(wcat, 0, 256, F3, bs512, 64, 256, pq, nullptr, nullptr, nullptr);
    k_gmax<128><<<dim3(N / 2, B), thr>>>(pq, idxp, gs[2], bs[2], xc, 128);

    // ---- stage 4: F=xc[128:256], C=128, O=256, choff=256 ----
    const float* F4 = xc + (size_t)128 * N;
    k_wprep<<<128, thr>>>(W4, 256, 128, wcat);
    k_xx<<<dim3(N / 256, B), thr>>>(F4, bs512, 128, xxp);
    k_knn<128><<<knng, thr, knn_smem(128)>>>(F4, bs512, xxp, idxp);
    k_g128<1><<<dim3(16, 4, B), thr>>>(wcat, 0, 512, F4, bs512, 128, 512, pq, nullptr, nullptr, nullptr);
    k_gmax<256><<<dim3(N, B), thr>>>(pq, idxp, gs[3], bs[3], xc, 256);

    // ---- conv5 (+fused partial pooling) + head ----
    k_trs<<<2048, thr>>>(W5, 512, 1024, 512, w5t);
    k_g128<2><<<dim3(16, 8, B), thr>>>(w5t, 0, 1024, xc, bs512, 512, 1024, nullptr, gs[4], bs[4], partp);
    k_pool2<<<(B * 1024) / 256, thr>>>(partp, poolp);
    k_fc<1><<<(16 * 512 * 32) / 256, thr>>>(poolp, 2048, L1w, nullptr, gs[5], bs[5], 512, h1);
    k_fc<1><<<(16 * 256 * 32) / 256, thr>>>(h1, 512, L2w, L2b, gs[6], bs[6], 256, h2);
    k_fc<0><<<(16 * 40 * 32 + 255) / 256, thr>>>(h2, 256, L3w, L3b, nullptr, nullptr, 40, out);
}

// round 17
// speedup vs baseline: 1.2142x; 1.1256x over previous
#include <cuda_runtime.h>
#include <cuda_bf16.h>
#include <cstdint>

#define BNS 0.9999950000375f  // 1/sqrt(1+1e-5)
constexpr int B = 16;
constexpr int N = 2048;

// ----------------- device scratch (no allocations) -----------------
__device__ float  g_xx[B * N];
__device__ int    g_idx[B * N * 20];
__device__ float  g_xc[(size_t)B * 512 * N];        // channel-major concat feats
__device__ float  g_pq[(size_t)B * N * 512];        // point-major P|Q per stage
__device__ float2 g_part[(size_t)B * 1024 * 16];    // conv5 partial (max,sum) per col-tile
__device__ float  g_wcat[128 * 512];                // Wt_cat: C x 2O
__device__ float  g_w5t[512 * 1024];
__device__ float  g_pool[B * 2048];
__device__ float  g_h1[B * 512];
__device__ float  g_h2[B * 256];
__device__ __nv_bfloat16 g_fh[(size_t)B * 128 * N]; // split-bf16 hi
__device__ __nv_bfloat16 g_fl[(size_t)B * 128 * N]; // split-bf16 lo

// ----------------- mma helpers -----------------
__device__ __forceinline__ uint32_t s2u(const void* p) {
    return (uint32_t)__cvta_generic_to_shared(p);
}
__device__ __forceinline__ void ldsm4(uint32_t* r, uint32_t a) {
    asm volatile("ldmatrix.sync.aligned.m8n8.x4.shared.b16 {%0,%1,%2,%3}, [%4];"
                 : "=r"(r[0]), "=r"(r[1]), "=r"(r[2]), "=r"(r[3]) : "r"(a));
}
__device__ __forceinline__ void ldsm2(uint32_t* r, uint32_t a) {
    asm volatile("ldmatrix.sync.aligned.m8n8.x2.shared.b16 {%0,%1}, [%2];"
                 : "=r"(r[0]), "=r"(r[1]) : "r"(a));
}
__device__ __forceinline__ void mma16816(float* d, const uint32_t* a, const uint32_t* b) {
    asm volatile("mma.sync.aligned.m16n8k16.row.col.f32.bf16.bf16.f32 "
                 "{%0,%1,%2,%3},{%4,%5,%6,%7},{%8,%9},{%0,%1,%2,%3};"
                 : "+f"(d[0]), "+f"(d[1]), "+f"(d[2]), "+f"(d[3])
                 : "r"(a[0]), "r"(a[1]), "r"(a[2]), "r"(a[3]), "r"(b[0]), "r"(b[1]));
}

// ----------------- helpers -----------------
__global__ void k_wprep(const float* __restrict__ W, int O, int C, float* __restrict__ Wt) {
    int t = blockIdx.x * 256 + threadIdx.x;
    if (t >= O * C) return;
    int o = t / C, c = t - o * C;
    float wd = W[(size_t)o * 2 * C + c];
    float wc = W[(size_t)o * 2 * C + C + c];
    Wt[(size_t)c * 2 * O + o] = wd;
    Wt[(size_t)c * 2 * O + O + o] = wc - wd;
}

__global__ void k_trs(const float* __restrict__ W, int rstride, int O, int C,
                      float* __restrict__ Wt) {
    int t = blockIdx.x * 256 + threadIdx.x;
    if (t >= O * C) return;
    int o = t / C, c = t - o * C;
    Wt[(size_t)c * O + o] = W[(size_t)o * rstride + c];
}

__global__ void k_xx(const float* __restrict__ F, size_t bstride, int C,
                     float* __restrict__ xx) {
    int b = blockIdx.y, i = blockIdx.x * 256 + threadIdx.x;
    const float* Fb = F + (size_t)b * bstride;
    float s = 0.f;
    for (int c = 0; c < C; c++) { float v = Fb[(size_t)c * N + i]; s = fmaf(v, v, s); }
    xx[b * N + i] = s;
}

// split fp32 -> bf16 hi + bf16 residual (channel-major contiguous C*N block per batch)
__global__ void k_split(const float* __restrict__ F, size_t bstride, int CN,
                        __nv_bfloat16* __restrict__ fh, __nv_bfloat16* __restrict__ fl) {
    int b = blockIdx.y, i = blockIdx.x * 256 + threadIdx.x;
    if (i >= CN) return;
    float v = F[(size_t)b * bstride + i];
    __nv_bfloat16 h = __float2bfloat16_rn(v);
    fh[(size_t)b * CN + i] = h;
    fl[(size_t)b * CN + i] = __float2bfloat16_rn(v - __bfloat162float(h));
}

// ----------------- fp32 kNN (stage 1, C=3 only) -----------------
template <int C>
__global__ __launch_bounds__(256, 2) void k_knn(const float* __restrict__ F, size_t bstride,
                                                const float* __restrict__ xx,
                                                int* __restrict__ idxo) {
    constexpr int KC = (C < 32) ? C : 32;
    extern __shared__ float sm[];
    float* As  = sm;
    float* Bs  = As + C * 64;
    float* sD  = Bs + KC * 128;
    float* sXj = sD + 64 * 132;
    int b = blockIdx.y, i0 = blockIdx.x * 64;
    const float* Fb = F + (size_t)b * bstride;
    int tid = threadIdx.x, lane = tid & 31, w = tid >> 5;
    int tx = tid & 15, ty = tid >> 4;

    for (int t = tid; t < C * 64; t += 256)
        As[t] = Fb[(size_t)(t >> 6) * N + i0 + (t & 63)];

    float val[8]; int idx[8]; float th[8];
#pragma unroll
    for (int r = 0; r < 8; r++) { val[r] = -3e38f; idx[r] = 0; th[r] = -3e38f; }

    for (int j0 = 0; j0 < N; j0 += 128) {
        __syncthreads();
        if (tid < 128) sXj[tid] = xx[b * N + j0 + tid];
        float acc[4][8] = {};
        for (int c0 = 0; c0 < C; c0 += KC) {
            if (c0) __syncthreads();
            for (int t = tid; t < KC * 128; t += 256)
                Bs[t] = Fb[(size_t)(c0 + (t >> 7)) * N + j0 + (t & 127)];
            __syncthreads();
#pragma unroll
            for (int kk = 0; kk < KC; kk++) {
                float4 a4 = *(const float4*)&As[(c0 + kk) * 64 + ty * 4];
                float4 b0 = *(const float4*)&Bs[kk * 128 + tx * 4];
                float4 b1 = *(const float4*)&Bs[kk * 128 + 64 + tx * 4];
                float a[4] = {a4.x, a4.y, a4.z, a4.w};
                float bv[8] = {b0.x, b0.y, b0.z, b0.w, b1.x, b1.y, b1.z, b1.w};
#pragma unroll
                for (int i = 0; i < 4; i++)
#pragma unroll
                    for (int j = 0; j < 8; j++) acc[i][j] = fmaf(a[i], bv[j], acc[i][j]);
            }
        }
        __syncthreads();
#pragma unroll
        for (int ii = 0; ii < 4; ii++)
#pragma unroll
            for (int jj = 0; jj < 8; jj++) {
                int cl = (jj < 4) ? (tx * 4 + jj) : (64 + tx * 4 + jj - 4);
                sD[(ty * 4 + ii) * 132 + cl] = 2.f * acc[ii][jj] - sXj[cl];
            }
        __syncthreads();
#pragma unroll
        for (int r = 0; r < 8; r++) {
            int row = (w << 3) + r;
#pragma unroll
            for (int h = 0; h < 4; h++) {
                float d = sD[row * 132 + h * 32 + lane];
                unsigned ball = __ballot_sync(0xffffffffu, d > th[r]);
                while (ball) {
                    int src = __ffs(ball) - 1;
                    ball &= ball - 1;
                    float xv = __shfl_sync(0xffffffffu, d, src);
                    if (xv <= th[r]) continue;
                    int xj = j0 + h * 32 + src;
                    unsigned bigger = __ballot_sync(0xffffffffu, val[r] > xv);
                    int pos = __popc(bigger & 0xFFFFFu);
                    float upv = __shfl_up_sync(0xffffffffu, val[r], 1);
                    int   upi = __shfl_up_sync(0xffffffffu, idx[r], 1);
                    if (lane == pos)     { val[r] = xv;  idx[r] = xj; }
                    else if (lane > pos) { val[r] = upv; idx[r] = upi; }
                    th[r] = __shfl_sync(0xffffffffu, val[r], 19);
                }
            }
        }
    }
    if (lane < 20) {
#pragma unroll
        for (int r = 0; r < 8; r++)
            idxo[((size_t)b * N + i0 + (w << 3) + r) * 20 + lane] = idx[r];
    }
}

// ----------------- tensor-core kNN (split-bf16, 3-pass mma.sync) -----------------
// Block: 64 i-rows x 128 j-cols per tile. Warp = 32x32 sub-tile (mw=w>>2, nw=w&3).
template <int C>
__global__ __launch_bounds__(256) void k_knn_tc(const __nv_bfloat16* __restrict__ Fh,
                                                const __nv_bfloat16* __restrict__ Fl,
                                                const float* __restrict__ xx,
                                                int* __restrict__ idxo) {
    constexpr int KC = 32, AP = C + 8, BP = KC + 8;
    extern __shared__ char smraw[];
    __nv_bfloat16* sAh = (__nv_bfloat16*)smraw;
    __nv_bfloat16* sAl = sAh + 64 * AP;
    __nv_bfloat16* sBh = sAl + 64 * AP;
    __nv_bfloat16* sBl = sBh + 128 * BP;
    float* sD  = (float*)(sBl + 128 * BP);
    float* sXj = sD + 64 * 132;

    int b = blockIdx.y, i0 = blockIdx.x * 64;
    const __nv_bfloat16* Fbh = Fh + (size_t)b * C * N;
    const __nv_bfloat16* Fbl = Fl + (size_t)b * C * N;
    int tid = threadIdx.x, lane = tid & 31, w = tid >> 5;
    int mw = w >> 2, nw = w & 3;

    for (int t = tid; t < C * 64; t += 256) {
        int i = t & 63, c = t >> 6;
        sAh[i * AP + c] = Fbh[(size_t)c * N + i0 + i];
        sAl[i * AP + c] = Fbl[(size_t)c * N + i0 + i];
    }

    float val[8]; int idx[8]; float th[8];
#pragma unroll
    for (int r = 0; r < 8; r++) { val[r] = -3e38f; idx[r] = 0; th[r] = -3e38f; }

    int lrow = ((lane >> 3) & 1) * 8 + (lane & 7);   // A ldmatrix row
    int koff = (lane >> 4) * 8;                      // A ldmatrix k offset
    int brow = lane & 7;                             // B ldmatrix row (lanes mod 16)
    int bko  = ((lane >> 3) & 1) * 8;

    for (int j0 = 0; j0 < N; j0 += 128) {
        float acc[2][4][4] = {};
        for (int c0 = 0; c0 < C; c0 += KC) {
            __syncthreads();
            if (c0 == 0 && tid < 128) sXj[tid] = xx[b * N + j0 + tid];
            for (int t = tid; t < KC * 128; t += 256) {
                int kk = t >> 7, j = t & 127;
                sBh[j * BP + kk] = Fbh[(size_t)(c0 + kk) * N + j0 + j];
                sBl[j * BP + kk] = Fbl[(size_t)(c0 + kk) * N + j0 + j];
            }
            __syncthreads();
#pragma unroll
            for (int kk = 0; kk < KC; kk += 16) {
                uint32_t ah[2][4], al[2][4], bh[4][2], bl[4][2];
#pragma unroll
                for (int a = 0; a < 2; a++) {
                    int row = 32 * mw + 16 * a + lrow;
                    ldsm4(ah[a], s2u(sAh + row * AP + c0 + kk + koff));
                    ldsm4(al[a], s2u(sAl + row * AP + c0 + kk + koff));
                }
#pragma unroll
                for (int t4 = 0; t4 < 4; t4++) {
                    int row = 32 * nw + 8 * t4 + brow;
                    ldsm2(bh[t4], s2u(sBh + row * BP + kk + bko));
                    ldsm2(bl[t4], s2u(sBl + row * BP + kk + bko));
                }
#pragma unroll
                for (int a = 0; a < 2; a++)
#pragma unroll
                    for (int t4 = 0; t4 < 4; t4++) {
                        mma16816(acc[a][t4], ah[a], bh[t4]);
                        mma16816(acc[a][t4], ah[a], bl[t4]);
                        mma16816(acc[a][t4], al[a], bh[t4]);
                    }
            }
        }
        // epilogue: D = 2*inner - xx_j into sD
        int r0 = lane >> 2, cb = 2 * (lane & 3);
#pragma unroll
        for (int a = 0; a < 2; a++)
#pragma unroll
            for (int t4 = 0; t4 < 4; t4++) {
                int row = 32 * mw + 16 * a + r0;
                int col = 32 * nw + 8 * t4 + cb;
                sD[row * 132 + col]           = 2.f * acc[a][t4][0] - sXj[col];
                sD[row * 132 + col + 1]       = 2.f * acc[a][t4][1] - sXj[col + 1];
                sD[(row + 8) * 132 + col]     = 2.f * acc[a][t4][2] - sXj[col];
                sD[(row + 8) * 132 + col + 1] = 2.f * acc[a][t4][3] - sXj[col + 1];
            }
        __syncthreads();
        // selection: warp w owns rows 8w..8w+7
#pragma unroll
        for (int r = 0; r < 8; r++) {
            int row = (w << 3) + r;
#pragma unroll
            for (int h = 0; h < 4; h++) {
                float d = sD[row * 132 + h * 32 + lane];
                unsigned ball = __ballot_sync(0xffffffffu, d > th[r]);
                while (ball) {
                    int src = __ffs(ball) - 1;
                    ball &= ball - 1;
                    float xv = __shfl_sync(0xffffffffu, d, src);
                    if (xv <= th[r]) continue;
                    int xj = j0 + h * 32 + src;
                    unsigned bigger = __ballot_sync(0xffffffffu, val[r] > xv);
                    int pos = __popc(bigger & 0xFFFFFu);
                    float upv = __shfl_up_sync(0xffffffffu, val[r], 1);
                    int   upi = __shfl_up_sync(0xffffffffu, idx[r], 1);
                    if (lane == pos)     { val[r] = xv;  idx[r] = xj; }
                    else if (lane > pos) { val[r] = upv; idx[r] = upi; }
                    th[r] = __shfl_sync(0xffffffffu, val[r], 19);
                }
            }
        }
    }
    if (lane < 20) {
#pragma unroll
        for (int r = 0; r < 8; r++)
            idxo[((size_t)b * N + i0 + (w << 3) + r) * 20 + lane] = idx[r];
    }
}

// ----------------- 128x128 tiled GEMM, 8x8/thread, double-buffered smem -----------------
template <int EPI>
__global__ __launch_bounds__(256, 2) void k_g128(
    const float* __restrict__ A, size_t a_bs, int lda,
    const float* __restrict__ Bm, size_t b_bs,
    int C, int M, float* __restrict__ out,
    const float* __restrict__ e1, const float* __restrict__ e2,
    float2* __restrict__ part) {
    __shared__ float sA[2][8][128];
    __shared__ float sB[2][8][128];
    __shared__ float redm[128 * 16];
    __shared__ float reds[128 * 16];
    int b = blockIdx.z, o0 = blockIdx.y * 128, n0 = blockIdx.x * 128;
    const float* Ab = A + (size_t)b * a_bs;
    const float* Bb = Bm + (size_t)b * b_bs;
    int tid = threadIdx.x, tx = tid & 15, ty = tid >> 4;
    int lr = tid >> 5, lc = (tid & 31) * 4;
    float acc[8][8] = {};
    int T = (C + 7) / 8;
    float4 ra = make_float4(0.f, 0.f, 0.f, 0.f), rb = ra;
    if (lr < C) {
        ra = *(const float4*)&Ab[(size_t)lr * lda + o0 + lc];
        rb = *(const float4*)&Bb[(size_t)lr * N + n0 + lc];
    }
    int p = 0;
    for (int t = 0; t < T; t++) {
        *(float4*)&sA[p][lr][lc] = ra;
        *(float4*)&sB[p][lr][lc] = rb;
        __syncthreads();
        if (t + 1 < T) {
            int c = (t + 1) * 8 + lr;
            ra = make_float4(0.f, 0.f, 0.f, 0.f); rb = ra;
            if (c < C) {
                ra = *(const float4*)&Ab[(size_t)c * lda + o0 + lc];
                rb = *(const float4*)&Bb[(size_t)c * N + n0 + lc];
            }
        }
#pragma unroll
        for (int kk = 0; kk < 8; kk++) {
            float a[8], bv[8];
            *(float4*)&a[0]  = *(const float4*)&sA[p][kk][ty * 8];
            *(float4*)&a[4]  = *(const float4*)&sA[p][kk][ty * 8 + 4];
            *(float4*)&bv[0] = *(const float4*)&sB[p][kk][tx * 4];
            *(float4*)&bv[4] = *(const float4*)&sB[p][kk][64 + tx * 4];
#pragma unroll
            for (int i = 0; i < 8; i++)
#pragma unroll
                for (int j = 0; j < 8; j++) acc[i][j] = fmaf(a[i], bv[j], acc[i][j]);
        }
        p ^= 1;
    }
    if (EPI == 1) {
#pragma unroll
        for (int j = 0; j < 8; j++) {
            int col = n0 + ((j < 4) ? (tx * 4 + j) : (64 + tx * 4 + j - 4));
            float* oc = out + ((size_t)b * N + col) * M + o0 + ty * 8;
            float4 v0 = make_float4(acc[0][j], acc[1][j], acc[2][j], acc[3][j]);
            float4 v1 = make_float4(acc[4][j], acc[5][j], acc[6][j], acc[7][j]);
            *(float4*)&oc[0] = v0;
            *(float4*)&oc[4] = v1;
        }
    } else {
#pragma unroll
        for (int i = 0; i < 8; i++) {
            int row = o0 + ty * 8 + i;
            float s = e1[row] * BNS, bi = e2[row];
            float mx = -3e38f, sm = 0.f;
#pragma unroll
            for (int j = 0; j < 8; j++) {
                float v = acc[i][j] * s + bi;
                v = v < 0.f ? 0.2f * v : v;
                mx = fmaxf(mx, v); sm += v;
            }
            redm[(ty * 8 + i) * 16 + tx] = mx;
            reds[(ty * 8 + i) * 16 + tx] = sm;
        }
        __syncthreads();
        if (tid < 128) {
            float mx = -3e38f, sm = 0.f;
#pragma unroll
            for (int t = 0; t < 16; t++) {
                mx = fmaxf(mx, redm[tid * 16 + t]);
                sm += reds[tid * 16 + t];
            }
            part[((size_t)b * M + o0 + tid) * 16 + blockIdx.x] = make_float2(mx, sm);
        }
    }
}

// ----------------- gather-max + BN + lrelu -----------------
template <int O>
__global__ void k_gmax(const float* __restrict__ PQ, const int* __restrict__ idx,
                       const float* __restrict__ g, const float* __restrict__ bb,
                       float* __restrict__ xc, int choff) {
    constexpr int PTS = 256 / O;
    int b = blockIdx.y;
    int n = blockIdx.x * PTS + (threadIdx.x >> (O == 64 ? 6 : (O == 128 ? 7 : 8)));
    int o = threadIdx.x & (O - 1);
    const float* Pb = PQ + (size_t)b * N * (2 * O);
    const int* ir = idx + ((size_t)b * N + n) * 20;
    float m = -3e38f;
#pragma unroll
    for (int k = 0; k < 20; k++) {
        int j = __ldg(&ir[k]);
        m = fmaxf(m, __ldg(&Pb[(size_t)j * (2 * O) + o]));
    }
    float v = m + Pb[(size_t)n * (2 * O) + O + o];
    v = v * (g[o] * BNS) + bb[o];
    v = v < 0.f ? 0.2f * v : v;
    xc[((size_t)b * 512 + choff + o) * N + n] = v;
}

// ----------------- final pooling reduce + FC head -----------------
__global__ void k_pool2(const float2* __restrict__ part, float* __restrict__ p) {
    int t = blockIdx.x * 256 + threadIdx.x;
    int b = t >> 10, o = t & 1023;
    const float2* pr = part + (size_t)t * 16;
    float mx = -3e38f, s = 0.f;
#pragma unroll
    for (int i = 0; i < 16; i++) { float2 v = pr[i]; mx = fmaxf(mx, v.x); s += v.y; }
    p[b * 2048 + o] = mx;
    p[b * 2048 + 1024 + o] = s * (1.f / 2048.f);
}

template <int MODE>
__global__ void k_fc(const float* __restrict__ in, int Cin, const float* __restrict__ W,
                     const float* __restrict__ bias, const float* __restrict__ g,
                     const float* __restrict__ bb, int O, float* __restrict__ outp) {
    int gw = (blockIdx.x * blockDim.x + threadIdx.x) >> 5;
    int lane = threadIdx.x & 31;
    if (gw >= 16 * O) return;
    int b = gw / O, o = gw - b * O;
    const float* ib = in + (size_t)b * Cin;
    const float* wr = W + (size_t)o * Cin;
    float s = 0.f;
    for (int c = lane; c < Cin; c += 32) s = fmaf(ib[c], wr[c], s);
#pragma unroll
    for (int off = 16; off; off >>= 1) s += __shfl_xor_sync(0xffffffffu, s, off);
    if (lane == 0) {
        float v = s + (bias ? bias[o] : 0.f);
        if (MODE == 1) { v = v * (g[o] * BNS) + bb[o]; v = v < 0.f ? 0.2f * v : v; }
        outp[b * O + o] = v;
    }
}

static int knn_smem(int C) {
    int kc = (C < 32) ? C : 32;
    return (C * 64 + kc * 128 + 64 * 132 + 128) * 4;
}
static int knn_tc_smem(int C) {
    int AP = C + 8, BP = 40;
    return 64 * AP * 2 * 2 + 128 * BP * 2 * 2 + 64 * 132 * 4 + 128 * 4;
}

extern "C" void kernel_launch(void* const* d_in, const int* in_sizes, int n_in,
                              void* d_out, int out_size) {
    (void)in_sizes; (void)n_in; (void)out_size;
    const float* x  = (const float*)d_in[0];
    const float* W1 = (const float*)d_in[1];
    const float* W2 = (const float*)d_in[2];
    const float* W3 = (const float*)d_in[3];
    const float* W4 = (const float*)d_in[4];
    const float* W5 = (const float*)d_in[5];
    const float *gs[7], *bs[7];
    for (int i = 0; i < 7; i++) { gs[i] = (const float*)d_in[6 + 2 * i]; bs[i] = (const float*)d_in[7 + 2 * i]; }
    const float* L1w = (const float*)d_in[20];
    const float* L2w = (const float*)d_in[21];
    const float* L2b = (const float*)d_in[22];
    const float* L3w = (const float*)d_in[23];
    const float* L3b = (const float*)d_in[24];
    float* out = (float*)d_out;

    float *xxp, *xc, *pq, *wcat, *w5t, *poolp, *h1, *h2;
    float2* partp;
    int* idxp;
    __nv_bfloat16 *fh, *fl;
    cudaGetSymbolAddress((void**)&xxp, g_xx);
    cudaGetSymbolAddress((void**)&idxp, g_idx);
    cudaGetSymbolAddress((void**)&xc, g_xc);
    cudaGetSymbolAddress((void**)&pq, g_pq);
    cudaGetSymbolAddress((void**)&partp, g_part);
    cudaGetSymbolAddress((void**)&wcat, g_wcat);
    cudaGetSymbolAddress((void**)&w5t, g_w5t);
    cudaGetSymbolAddress((void**)&poolp, g_pool);
    cudaGetSymbolAddress((void**)&h1, g_h1);
    cudaGetSymbolAddress((void**)&h2, g_h2);
    cudaGetSymbolAddress((void**)&fh, g_fh);
    cudaGetSymbolAddress((void**)&fl, g_fl);

    cudaFuncSetAttribute(k_knn<3>, cudaFuncAttributeMaxDynamicSharedMemorySize, knn_smem(3));
    cudaFuncSetAttribute(k_knn_tc<64>,  cudaFuncAttributeMaxDynamicSharedMemorySize, knn_tc_smem(64));
    cudaFuncSetAttribute(k_knn_tc<128>, cudaFuncAttributeMaxDynamicSharedMemorySize, knn_tc_smem(128));

    dim3 thr(256);
    dim3 knng(N / 64, B);
    size_t bs512 = (size_t)512 * N;

    // ---- stage 1: F=x, C=3, O=64, choff=0 (fp32 knn) ----
    k_wprep<<<1, thr>>>(W1, 64, 3, wcat);
    k_xx<<<dim3(N / 256, B), thr>>>(x, (size_t)3 * N, 3, xxp);
    k_knn<3><<<knng, thr, knn_smem(3)>>>(x, (size_t)3 * N, xxp, idxp);
    k_g128<1><<<dim3(16, 1, B), thr>>>(wcat, 0, 128, x, (size_t)3 * N, 3, 128, pq, nullptr, nullptr, nullptr);
    k_gmax<64><<<dim3(N / 4, B), thr>>>(pq, idxp, gs[0], bs[0], xc, 0);

    // ---- stage 2: F=xc[0:64], C=64, O=64, choff=64 ----
    const float* F2 = xc;
    k_wprep<<<16, thr>>>(W2, 64, 64, wcat);
    k_xx<<<dim3(N / 256, B), thr>>>(F2, bs512, 64, xxp);
    k_split<<<dim3(64 * N / 256, B), thr>>>(F2, bs512, 64 * N, fh, fl);
    k_knn_tc<64><<<knng, thr, knn_tc_smem(64)>>>(fh, fl, xxp, idxp);
    k_g128<1><<<dim3(16, 1, B), thr>>>(wcat, 0, 128, F2, bs512, 64, 128, pq, nullptr, nullptr, nullptr);
    k_gmax<64><<<dim3(N / 4, B), thr>>>(pq, idxp, gs[1], bs[1], xc, 64);

    // ---- stage 3: F=xc[64:128], C=64, O=128, choff=128 ----
    const float* F3 = xc + (size_t)64 * N;
    k_wprep<<<32, thr>>>(W3, 128, 64, wcat);
    k_xx<<<dim3(N / 256, B), thr>>>(F3, bs512, 64, xxp);
    k_split<<<dim3(64 * N / 256, B), thr>>>(F3, bs512, 64 * N, fh, fl);
    k_knn_tc<64><<<knng, thr, knn_tc_smem(64)>>>(fh, fl, xxp, idxp);
    k_g128<1><<<dim3(16, 2, B), thr>>>(wcat, 0, 256, F3, bs512, 64, 256, pq, nullptr, nullptr, nullptr);
    k_gmax<128><<<dim3(N / 2, B), thr>>>(pq, idxp, gs[2], bs[2], xc, 128);

    // ---- stage 4: F=xc[128:256], C=128, O=256, choff=256 ----
    const float* F4 = xc + (size_t)128 * N;
    k_wprep<<<128, thr>>>(W4, 256, 128, wcat);
    k_xx<<<dim3(N / 256, B), thr>>>(F4, bs512, 128, xxp);
    k_split<<<dim3(128 * N / 256, B), thr>>>(F4, bs512, 128 * N, fh, fl);
    k_knn_tc<128><<<knng, thr, knn_tc_smem(128)>>>(fh, fl, xxp, idxp);
    k_g128<1><<<dim3(16, 4, B), thr>>>(wcat, 0, 512, F4, bs512, 128, 512, pq, nullptr, nullptr, nullptr);
    k_gmax<256><<<dim3(N, B), thr>>>(pq, idxp, gs[3], bs[3], xc, 256);

    // ---- conv5 (+fused partial pooling) + head ----
    k_trs<<<2048, thr>>>(W5, 512, 1024, 512, w5t);
    k_g128<2><<<dim3(16, 8, B), thr>>>(w5t, 0, 1024, xc, bs512, 512, 1024, nullptr, gs[4], bs[4], partp);
    k_pool2<<<(B * 1024) / 256, thr>>>(partp, poolp);
    k_fc<1><<<(16 * 512 * 32) / 256, thr>>>(poolp, 2048, L1w, nullptr, gs[5], bs[5], 512, h1);
    k_fc<1><<<(16 * 256 * 32) / 256, thr>>>(h1, 512, L2w, L2b, gs[6], bs[6], 256, h2);
    k_fc<0><<<(16 * 40 * 32 + 255) / 256, thr>>>(h2, 256, L3w, L3b, nullptr, nullptr, 40, out);
}